// round 6
// baseline (speedup 1.0000x reference)
#include <cuda_runtime.h>

#define NPRIMES 168
#define TPB 256
#define COLS 256           // columns per tile (1 per thread)
#define TILES 2            // tiles per block (software pipeline depth)
#define GPI 11             // gather steps issued per stream iteration
#define TABN (NPRIMES * 1000)

// Interleaved (kernel, bias) table: one LDG.64 fetches both values.
__device__ float2 g_tab[TABN];

// Per-prime magic-mod descriptor (compile-time, constant memory):
//  magic = floor(2^32/p)+1  ->  k % p == k - p*umulhi(k, magic)   (k < 2^20)
struct PInfo { unsigned magic; int p; };

#define PRIME_LIST \
 X(2) X(3) X(5) X(7) X(11) X(13) X(17) X(19) X(23) X(29) \
 X(31) X(37) X(41) X(43) X(47) X(53) X(59) X(61) X(67) X(71) \
 X(73) X(79) X(83) X(89) X(97) X(101) X(103) X(107) X(109) X(113) \
 X(127) X(131) X(137) X(139) X(149) X(151) X(157) X(163) X(167) X(173) \
 X(179) X(181) X(191) X(193) X(197) X(199) X(211) X(223) X(227) X(229) \
 X(233) X(239) X(241) X(251) X(257) X(263) X(269) X(271) X(277) X(281) \
 X(283) X(293) X(307) X(311) X(313) X(317) X(331) X(337) X(347) X(349) \
 X(353) X(359) X(367) X(373) X(379) X(383) X(389) X(397) X(401) X(409) \
 X(419) X(421) X(431) X(433) X(439) X(443) X(449) X(457) X(461) X(463) \
 X(467) X(479) X(487) X(491) X(499) X(503) X(509) X(521) X(523) X(541) \
 X(547) X(557) X(563) X(569) X(571) X(577) X(587) X(593) X(599) X(601) \
 X(607) X(613) X(617) X(619) X(631) X(641) X(643) X(647) X(653) X(659) \
 X(661) X(673) X(677) X(683) X(691) X(701) X(709) X(719) X(727) X(733) \
 X(739) X(743) X(751) X(757) X(761) X(769) X(773) X(787) X(797) X(809) \
 X(811) X(821) X(823) X(827) X(829) X(839) X(853) X(857) X(859) X(863) \
 X(877) X(881) X(883) X(887) X(907) X(911) X(919) X(929) X(937) X(941) \
 X(947) X(953) X(967) X(971) X(977) X(983) X(991) X(997)

__constant__ PInfo C_PI[NPRIMES] = {
#define X(p) { 0xFFFFFFFFu / (unsigned)(p) + 1u, (p) },
  PRIME_LIST
#undef X
};

__global__ __launch_bounds__(256)
void interleave_tab(const float* __restrict__ kern, const float* __restrict__ bias)
{
    int i = blockIdx.x * 256 + threadIdx.x;
    if (i < TABN) g_tab[i] = make_float2(kern[i], bias[i]);
}

__global__ __launch_bounds__(TPB, 7)
void bwl_prime_main(const float* __restrict__ x,
                    float* __restrict__ out,
                    int N, int B)
{
    __shared__ float w_s[2][COLS];
    __shared__ float b_s[2][COLS];

    const int t    = threadIdx.x;
    const int base = blockIdx.x * (COLS * TILES);

    const int col4 = t & 63;                 // float4 column within tile
    const int rpg  = B >> 2;                 // rows per group (16 for B=64)
    const int rbeg = (t >> 6) * rpg;         // this thread's row-group start
    const size_t nv = (size_t)(N >> 2);

    // ---- Prologue: gather tile 0 (coalesced LDG.64, 2 lines/warp) ----
    float w = 0.f, a = 0.f;
    {
        const unsigned k = (unsigned)(base + t);
        const float2* __restrict__ row = g_tab;
#pragma unroll 8
        for (int i = 0; i < NPRIMES; ++i) {
            const PInfo pi = C_PI[i];
            int m = (int)(k - (unsigned)pi.p * __umulhi(k, pi.magic));
            float2 e = __ldg(row + m);
            w += e.x; a += e.y;
            row += 1000;
        }
    }

    int buf = 0;
    for (int tile = 0; tile < TILES; ++tile) {
        w_s[buf][t] = w;  b_s[buf][t] = a;
        __syncthreads();

        const float4 wv = *reinterpret_cast<const float4*>(&w_s[buf][col4 * 4]);
        const float4 bv = *reinterpret_cast<const float4*>(&b_s[buf][col4 * 4]);

        const int k0 = base + tile * COLS;
        const float4* __restrict__ xv = reinterpret_cast<const float4*>(x)
                                        + (size_t)rbeg * nv + (k0 >> 2) + col4;
        float4* __restrict__       ov = reinterpret_cast<float4*>(out)
                                        + (size_t)rbeg * nv + (k0 >> 2) + col4;

        // Gather state for the NEXT tile, interleaved into the stream loop.
        const bool more = (tile + 1 < TILES);
        const unsigned kn = (unsigned)(k0 + COLS + t);
        float wn = 0.f, an = 0.f;
        int g = 0;
        const float2* __restrict__ rown = g_tab;

#pragma unroll 4
        for (int r = 0; r < rpg; ++r) {
            // stream: DRAM-bound float4 in / float4 out
            float4 xi = __ldcs(xv);

            // gather: GPI L1/L2-bound table loads issued while xi is in flight
            if (more) {
#pragma unroll
                for (int j = 0; j < GPI; ++j) {
                    if (g < NPRIMES) {
                        const PInfo pi = C_PI[g];
                        int m = (int)(kn - (unsigned)pi.p * __umulhi(kn, pi.magic));
                        float2 e = __ldg(rown + m);
                        wn += e.x; an += e.y;
                    }
                    ++g;
                    rown += 1000;
                }
            }

            float4 o;
            o.x = fmaf(xi.x, wv.x, bv.x);
            o.y = fmaf(xi.y, wv.y, bv.y);
            o.z = fmaf(xi.z, wv.z, bv.z);
            o.w = fmaf(xi.w, wv.w, bv.w);
            __stcs(ov, o);
            xv += nv;
            ov += nv;
        }

        // epilogue: finish any remaining gathers (robust for small rpg)
        if (more) {
            while (g < NPRIMES) {
                const PInfo pi = C_PI[g];
                int m = (int)(kn - (unsigned)pi.p * __umulhi(kn, pi.magic));
                float2 e = __ldg(rown + m);
                wn += e.x; an += e.y;
                ++g;
                rown += 1000;
            }
        }

        w = wn; a = an;
        buf ^= 1;
    }
}

extern "C" void kernel_launch(void* const* d_in, const int* in_sizes, int n_in,
                              void* d_out, int out_size)
{
    const float* x  = (const float*)d_in[0];   // (B, N) float32
    const float* kr = (const float*)d_in[1];   // (168, 1000) float32
    const float* br = (const float*)d_in[2];   // (168, 1000) float32
    float* out = (float*)d_out;

    const int N = 524288;
    const int B = in_sizes[0] / N;             // 64

    interleave_tab<<<(TABN + 255) / 256, 256>>>(kr, br);

    const int grid = N / (COLS * TILES);       // 1024 blocks, ~1 wave
    bwl_prime_main<<<grid, TPB>>>(x, out, N, B);
}

// round 7
// speedup vs baseline: 1.3000x; 1.3000x over previous
#include <cuda_runtime.h>

#define NPRIMES 168
#define TPB 128
#define COLS 128          // 1 column per thread
#define TABN (NPRIMES * 1000)

// Interleaved (kernel, bias) table: one LDG.64 fetches both values.
__device__ float2 g_tab[TABN];

// Per-prime magic-mod descriptor (compile-time, constant memory):
//  magic = floor(2^32/p)+1  ->  k % p == k - p*umulhi(k, magic)   (k < 2^20)
struct PInfo { unsigned magic; int p; };

#define PRIME_LIST \
 X(2) X(3) X(5) X(7) X(11) X(13) X(17) X(19) X(23) X(29) \
 X(31) X(37) X(41) X(43) X(47) X(53) X(59) X(61) X(67) X(71) \
 X(73) X(79) X(83) X(89) X(97) X(101) X(103) X(107) X(109) X(113) \
 X(127) X(131) X(137) X(139) X(149) X(151) X(157) X(163) X(167) X(173) \
 X(179) X(181) X(191) X(193) X(197) X(199) X(211) X(223) X(227) X(229) \
 X(233) X(239) X(241) X(251) X(257) X(263) X(269) X(271) X(277) X(281) \
 X(283) X(293) X(307) X(311) X(313) X(317) X(331) X(337) X(347) X(349) \
 X(353) X(359) X(367) X(373) X(379) X(383) X(389) X(397) X(401) X(409) \
 X(419) X(421) X(431) X(433) X(439) X(443) X(449) X(457) X(461) X(463) \
 X(467) X(479) X(487) X(491) X(499) X(503) X(509) X(521) X(523) X(541) \
 X(547) X(557) X(563) X(569) X(571) X(577) X(587) X(593) X(599) X(601) \
 X(607) X(613) X(617) X(619) X(631) X(641) X(643) X(647) X(653) X(659) \
 X(661) X(673) X(677) X(683) X(691) X(701) X(709) X(719) X(727) X(733) \
 X(739) X(743) X(751) X(757) X(761) X(769) X(773) X(787) X(797) X(809) \
 X(811) X(821) X(823) X(827) X(829) X(839) X(853) X(857) X(859) X(863) \
 X(877) X(881) X(883) X(887) X(907) X(911) X(919) X(929) X(937) X(941) \
 X(947) X(953) X(967) X(971) X(977) X(983) X(991) X(997)

__constant__ PInfo C_PI[NPRIMES] = {
#define X(p) { 0xFFFFFFFFu / (unsigned)(p) + 1u, (p) },
  PRIME_LIST
#undef X
};

__global__ __launch_bounds__(256)
void interleave_tab(const float* __restrict__ kern, const float* __restrict__ bias)
{
    int i = blockIdx.x * 256 + threadIdx.x;
    if (i < TABN) g_tab[i] = make_float2(kern[i], bias[i]);
}

__global__ __launch_bounds__(TPB, 16)
void bwl_prime_main(const float* __restrict__ x,
                    float* __restrict__ out,
                    int N, int B)
{
    __shared__ float w_s[COLS];
    __shared__ float b_s[COLS];

    const int t  = threadIdx.x;
    const int k0 = blockIdx.x * COLS;
    const unsigned k = (unsigned)(k0 + t);     // this thread's column

    // ---- Phase A: gather w/b, one column per thread ----
    // Lane-consecutive residues -> coalesced LDG.64 (2 lines/warp).
    float w = 0.f, a = 0.f;
    const float2* __restrict__ row = g_tab;

#pragma unroll 8
    for (int i = 0; i < NPRIMES; ++i) {
        const PInfo pi = C_PI[i];               // uniform constant read
        int m = (int)(k - (unsigned)pi.p * __umulhi(k, pi.magic));  // k % p
        float2 e = __ldg(row + m);
        w += e.x; a += e.y;
        row += 1000;
    }

    w_s[t] = w;  b_s[t] = a;
    __syncthreads();

    // ---- Phase B: stream; 4 row-groups x 32 float4-columns ----
    const int col4 = t & 31;                    // float4 column within block
    const int rpg  = B >> 2;                    // rows per group (16)
    const int rbeg = (t >> 5) * rpg;

    const float4 wv = *reinterpret_cast<const float4*>(&w_s[col4 * 4]);
    const float4 bv = *reinterpret_cast<const float4*>(&b_s[col4 * 4]);

    const size_t nv = (size_t)(N >> 2);
    const float4* __restrict__ xv = reinterpret_cast<const float4*>(x)
                                    + (size_t)rbeg * nv + (k0 >> 2) + col4;
    float4* __restrict__       ov = reinterpret_cast<float4*>(out)
                                    + (size_t)rbeg * nv + (k0 >> 2) + col4;

#pragma unroll 8
    for (int r = 0; r < rpg; ++r) {
        float4 xi = __ldcs(xv);
        float4 o;
        o.x = fmaf(xi.x, wv.x, bv.x);
        o.y = fmaf(xi.y, wv.y, bv.y);
        o.z = fmaf(xi.z, wv.z, bv.z);
        o.w = fmaf(xi.w, wv.w, bv.w);
        __stcs(ov, o);
        xv += nv;
        ov += nv;
    }
}

extern "C" void kernel_launch(void* const* d_in, const int* in_sizes, int n_in,
                              void* d_out, int out_size)
{
    const float* x  = (const float*)d_in[0];   // (B, N) float32
    const float* kr = (const float*)d_in[1];   // (168, 1000) float32
    const float* br = (const float*)d_in[2];   // (168, 1000) float32
    float* out = (float*)d_out;

    const int N = 524288;
    const int B = in_sizes[0] / N;             // 64

    interleave_tab<<<(TABN + 255) / 256, 256>>>(kr, br);

    const int grid = N / COLS;                 // 4096 blocks -> ~3.5 waves
    bwl_prime_main<<<grid, TPB>>>(x, out, N, B);
}